// round 13
// baseline (speedup 1.0000x reference)
#include <cuda_runtime.h>
#include <math.h>

#define NRAYS 16384
#define NSEG 8           // segments per ray, combined in-block via smem
#define PTS_PER_SEG 32   // points per segment (NSEG*PTS_PER_SEG = 256)
#define IMG_DIM 128

// -------- device scratch (no allocations allowed) --------
__device__ float g_gray[NRAYS];
// Initializers are load-bearing: the first invocation reads these, and the
// last finalize block resets them to the same values for replay.
__device__ double g_sum = 0.0, g_sumsq = 0.0;
__device__ unsigned g_minkey = 0xFFFFFFFFu;
__device__ unsigned g_maxkey = 0u;
__device__ unsigned g_count = 0u;

// -------- ordered-float key for atomicMin/Max --------
__device__ __forceinline__ unsigned fkey(float f) {
    unsigned u = __float_as_uint(f);
    return (u & 0x80000000u) ? ~u : (u | 0x80000000u);
}
__device__ __forceinline__ float funkey(unsigned k) {
    return (k & 0x80000000u) ? __uint_as_float(k & 0x7FFFFFFFu)
                             : __uint_as_float(~k);
}

__device__ __forceinline__ float lerpf(float a, float b, float t) {
    return fmaf(t, b - a, a);
}

// -------- interior fast sample: no bounds checks (caller guarantees) ------
__device__ __forceinline__ void sample_fast(const float* __restrict__ img,
                                            const float* __restrict__ opa,
                                            float fx, float fy, float fz,
                                            float& f, float& d) {
    float x0 = floorf(fx), y0 = floorf(fy), z0 = floorf(fz);
    float wx = fx - x0, wy = fy - y0, wz = fz - z0;
    int base = ((int)z0 << 14) + ((int)y0 << 7) + (int)x0;
    const float* p_ = img + base;
    float f000 = __ldg(p_), f001 = __ldg(p_ + 1);
    float f010 = __ldg(p_ + 128), f011 = __ldg(p_ + 129);
    float f100 = __ldg(p_ + 16384), f101 = __ldg(p_ + 16385);
    float f110 = __ldg(p_ + 16512), f111 = __ldg(p_ + 16513);
    const float* q_ = opa + base;
    float d000 = __ldg(q_), d001 = __ldg(q_ + 1);
    float d010 = __ldg(q_ + 128), d011 = __ldg(q_ + 129);
    float d100 = __ldg(q_ + 16384), d101 = __ldg(q_ + 16385);
    float d110 = __ldg(q_ + 16512), d111 = __ldg(q_ + 16513);
    float f00 = lerpf(f000, f001, wx), f01 = lerpf(f010, f011, wx);
    float f10 = lerpf(f100, f101, wx), f11 = lerpf(f110, f111, wx);
    float d00 = lerpf(d000, d001, wx), d01 = lerpf(d010, d011, wx);
    float d10 = lerpf(d100, d101, wx), d11 = lerpf(d110, d111, wx);
    float f0 = lerpf(f00, f01, wy), f1 = lerpf(f10, f11, wy);
    float d0 = lerpf(d00, d01, wy), d1 = lerpf(d10, d11, wy);
    f = lerpf(f0, f1, wz);
    d = lerpf(d0, d1, wz);
}

// -------- general sample: 3-way classified, fully inline ------------------
__device__ __forceinline__ void sample_any(const float* __restrict__ img,
                                           const float* __restrict__ opa,
                                           float fx, float fy, float fz,
                                           float& f, float& d) {
    if (fx >= 0.f && fx < 127.f && fy >= 0.f && fy < 127.f && fz >= 0.f &&
        fz < 127.f) {
        sample_fast(img, opa, fx, fy, fz, f, d);
    } else if (fx > -1.f && fx < 128.f && fy > -1.f && fy < 128.f &&
               fz > -1.f && fz < 128.f) {
        // boundary shell: inline predicated per-corner path
        float x0 = floorf(fx), y0 = floorf(fy), z0 = floorf(fz);
        int ix = (int)x0, iy = (int)y0, iz = (int)z0;
        float wx = fx - x0, wy = fy - y0, wz = fz - z0;
        f = 0.f;
        d = 0.f;
#pragma unroll
        for (int dz = 0; dz < 2; dz++) {
#pragma unroll
            for (int dy = 0; dy < 2; dy++) {
#pragma unroll
                for (int dx = 0; dx < 2; dx++) {
                    int X = ix + dx, Y = iy + dy, Z = iz + dz;
                    if ((unsigned)X < 128u && (unsigned)Y < 128u &&
                        (unsigned)Z < 128u) {
                        float wt = (dx ? wx : 1.f - wx) *
                                   (dy ? wy : 1.f - wy) *
                                   (dz ? wz : 1.f - wz);
                        int idx = (Z << 14) + (Y << 7) + X;
                        f += wt * __ldg(img + idx);
                        d += wt * __ldg(opa + idx);
                    }
                }
            }
        }
    } else {
        f = 0.f;
        d = 0.f;
    }
}

// slab interval helper: t range where all coords are within [lo, hi]
__device__ __forceinline__ void slab(float a, float b, float lo, float hi,
                                     float& tlo, float& thi) {
    if (fabsf(a) > 1e-12f) {
        float t1 = (lo - b) / a;
        float t2 = (hi - b) / a;
        tlo = fmaxf(tlo, fminf(t1, t2));
        thi = fminf(thi, fmaxf(t1, t2));
    } else if (b <= lo || b >= hi) {
        tlo = 1e30f;
        thi = -1e30f;
    }
}

// -------- fused render + in-block combine + stats --------
// grid: (4 w-groups, 128 rows); block: 256 threads = (32 w-lanes, 8 segments)
__global__ void __launch_bounds__(256)
render_kernel(const float* __restrict__ img, const float* __restrict__ opa,
              const float* __restrict__ Rm, const float* __restrict__ Tv) {
    int lane = threadIdx.x & 31;
    int segIdx = threadIdx.x >> 5;  // 0..7, one warp per segment row
    int w = blockIdx.x * 32 + lane;
    int h = blockIdx.y;

    // NDC grid: xs = linspace(1,-1,128) over w; ys likewise over h
    float gx = 1.f + (float)w * (-2.f / 127.f);
    float gy = 1.f + (float)h * (-2.f / 127.f);
    const float INV_FOCAL = 1.f / 1.7320508f;
    float dc0 = gx * INV_FOCAL, dc1 = gy * INV_FOCAL;  // dc2 = 1

    float R00 = Rm[0], R01 = Rm[1], R02 = Rm[2];
    float R10 = Rm[3], R11 = Rm[4], R12 = Rm[5];
    float R20 = Rm[6], R21 = Rm[7], R22 = Rm[8];
    float T0 = Tv[0], T1 = Tv[1], T2 = Tv[2];

    float dwx = dc0 * R00 + dc1 * R01 + R02;
    float dwy = dc0 * R10 + dc1 * R11 + R12;
    float dwz = dc0 * R20 + dc1 * R21 + R22;
    float ox = -(T0 * R00 + T1 * R01 + T2 * R02);
    float oy = -(T0 * R10 + T1 * R11 + T2 * R12);
    float oz = -(T0 * R20 + T1 * R21 + T2 * R22);

    // sample coord: fx = ((pos/half_extent)+1)*0.5*127 = pos*s + 63.5
    const float HE = 1.48828125f;  // (3/128)*127/2
    const float s = 63.5f / HE;
    float ax = dwx * s, bx = ox * s + 63.5f;
    float ay = dwy * s, by = oy * s + 63.5f;
    float az = dwz * s, bz = oz * s + 63.5f;

    int p0 = segIdx * PTS_PER_SEG;
    float dmin = 2.f + (float)p0 * (4.f / 255.f);
    float dmax = 2.f + (float)(p0 + PTS_PER_SEG - 1) * (4.f / 255.f);

    // conservative depth intervals (see R12): t_any (zero outside, margin
    // expands) and t_int (fast-path-safe inside, margin shrinks)
    float talo = -1e30f, tahi = 1e30f;
    float tilo = -1e30f, tihi = 1e30f;
    slab(ax, bx, -1.01f, 128.01f, talo, tahi);
    slab(ay, by, -1.01f, 128.01f, talo, tahi);
    slab(az, bz, -1.01f, 128.01f, talo, tahi);
    slab(ax, bx, 0.002f, 126.998f, tilo, tihi);
    slab(ay, by, 0.002f, 126.998f, tilo, tihi);
    slab(az, bz, 0.002f, 126.998f, tilo, tihi);

    float Tt = 1.f, acc = 0.f;

    if (dmax < talo || dmin > tahi) {
        // fully outside: (0,1) identity — skip all work
    } else if (dmin >= tilo && dmax <= tihi) {
        // whole segment interior: branch-free fast loop
#pragma unroll
        for (int g = 0; g < PTS_PER_SEG / 4; g++) {
            float fv[4], dv[4];
#pragma unroll
            for (int k = 0; k < 4; k++) {
                int p = p0 + g * 4 + k;
                float depth = 2.f + (float)p * (4.f / 255.f);
                sample_fast(img, opa, ax * depth + bx, ay * depth + by,
                            az * depth + bz, fv[k], dv[k]);
                dv[k] *= 0.1f;  // densities = opacity * SCALING
            }
#pragma unroll
            for (int k = 0; k < 4; k++) {
                // (1.0 + 1e-10) == 1.0f in fp32 (matches JAX fp32 trace)
                acc = fmaf(fv[k] * dv[k], Tt, acc);
                Tt *= (1.f - dv[k]);
            }
        }
    } else {
        // mixed segment: per-point 3-way classification
#pragma unroll
        for (int g = 0; g < PTS_PER_SEG / 4; g++) {
            float fv[4], dv[4];
#pragma unroll
            for (int k = 0; k < 4; k++) {
                int p = p0 + g * 4 + k;
                float depth = 2.f + (float)p * (4.f / 255.f);
                sample_any(img, opa, ax * depth + bx, ay * depth + by,
                           az * depth + bz, fv[k], dv[k]);
                dv[k] *= 0.1f;
            }
#pragma unroll
            for (int k = 0; k < 4; k++) {
                acc = fmaf(fv[k] * dv[k], Tt, acc);
                Tt *= (1.f - dv[k]);
            }
        }
    }

    // ---- in-block combine via smem (replaces the combine kernel) ----
    __shared__ float2 s_part[NSEG][32];
    s_part[segIdx][lane] = make_float2(acc, Tt);
    __syncthreads();

    if (threadIdx.x < 32) {
        float gray = 0.f, Tc = 1.f;
#pragma unroll
        for (int s2 = 0; s2 < NSEG; s2++) {
            float2 v = s_part[s2][lane];
            gray = fmaf(v.x, Tc, gray);
            Tc *= v.y;
        }
        g_gray[h * 128 + w] = gray;

        // warp reduction over the 32 rays of this block
        double sm = (double)gray;
        double sq = (double)gray * (double)gray;
        float mn = gray, mx = gray;
#pragma unroll
        for (int off = 16; off > 0; off >>= 1) {
            sm += __shfl_down_sync(0xFFFFFFFFu, sm, off);
            sq += __shfl_down_sync(0xFFFFFFFFu, sq, off);
            mn = fminf(mn, __shfl_down_sync(0xFFFFFFFFu, mn, off));
            mx = fmaxf(mx, __shfl_down_sync(0xFFFFFFFFu, mx, off));
        }
        if (lane == 0) {
            atomicAdd(&g_sum, sm);
            atomicAdd(&g_sumsq, sq);
            atomicMin(&g_minkey, fkey(mn));
            atomicMax(&g_maxkey, fkey(mx));
        }
    }
}

// -------- parallel normalize + transpose (16 blocks x 256, one tile each) --
__global__ void __launch_bounds__(256) finalize_kernel(float* __restrict__ out) {
    double sum = g_sum, sumsq = g_sumsq;
    double mean = sum / 16384.0;
    double var = (sumsq - sum * sum / 16384.0) / 16383.0;
    float stddev = (float)sqrt(var > 0.0 ? var : 0.0);
    float gmin = funkey(g_minkey), gmax = funkey(g_maxkey);
    float fmean = (float)mean;
    float inv = 1.f / (stddev + 1e-8f);
    float stmin = (gmin - fmean) * inv;
    float stmax = (gmax - fmean) * inv;
    float rng = 1.f / (stmax - stmin + 1e-8f);

    __shared__ float tile[32 * 33];
    int lane = threadIdx.x & 31, wid = threadIdx.x >> 5;
    int th = (blockIdx.x >> 2) * 32;
    int tw = (blockIdx.x & 3) * 32;
#pragma unroll
    for (int i = 0; i < 4; i++) {
        int rr = wid * 4 + i;
        float v = g_gray[(th + rr) * 128 + tw + lane];
        float vn = (v - fmean) * inv;
        tile[rr * 33 + lane] = (vn - stmin + 1e-8f) * rng;
    }
    __syncthreads();
#pragma unroll
    for (int i = 0; i < 4; i++) {
        int rr = wid * 4 + i;
        out[(tw + rr) * 128 + th + lane] = tile[lane * 33 + rr];
    }

    __threadfence();
    if (threadIdx.x == 0) {
        unsigned c = atomicAdd(&g_count, 1u);
        if (c == 15u) {
            g_sum = 0.0;
            g_sumsq = 0.0;
            g_minkey = 0xFFFFFFFFu;
            g_maxkey = 0u;
            g_count = 0u;
        }
    }
}

extern "C" void kernel_launch(void* const* d_in, const int* in_sizes, int n_in,
                              void* d_out, int out_size) {
    const float* img = (const float*)d_in[0];  // image3d [1,1,128,128,128]
    const float* opa = (const float*)d_in[1];  // opacity  [1,1,128,128,128]
    const float* Rm = (const float*)d_in[2];   // R [1,3,3]
    const float* Tv = (const float*)d_in[3];   // T [1,3]
    float* out = (float*)d_out;                // [1,1,128,128]

    render_kernel<<<dim3(4, IMG_DIM), 256>>>(img, opa, Rm, Tv);
    finalize_kernel<<<16, 256>>>(out);
}

// round 14
// speedup vs baseline: 1.3843x; 1.3843x over previous
#include <cuda_runtime.h>
#include <math.h>

#define NRAYS 16384
#define NSEG 32          // segments per ray = warps per block
#define PTS_PER_SEG 8    // points per segment (NSEG*PTS_PER_SEG = 256)
#define IMG_DIM 128

// -------- device scratch (no allocations allowed) --------
__device__ float g_gray[NRAYS];
// Initializers are load-bearing: the first invocation reads these, and the
// last finalize block resets them to the same values for replay.
__device__ double g_sum = 0.0, g_sumsq = 0.0;
__device__ unsigned g_minkey = 0xFFFFFFFFu;
__device__ unsigned g_maxkey = 0u;
__device__ unsigned g_count = 0u;

// -------- ordered-float key for atomicMin/Max --------
__device__ __forceinline__ unsigned fkey(float f) {
    unsigned u = __float_as_uint(f);
    return (u & 0x80000000u) ? ~u : (u | 0x80000000u);
}
__device__ __forceinline__ float funkey(unsigned k) {
    return (k & 0x80000000u) ? __uint_as_float(k & 0x7FFFFFFFu)
                             : __uint_as_float(~k);
}

__device__ __forceinline__ float lerpf(float a, float b, float t) {
    return fmaf(t, b - a, a);
}

// -------- interior fast sample: no bounds checks (caller guarantees) ------
__device__ __forceinline__ void sample_fast(const float* __restrict__ img,
                                            const float* __restrict__ opa,
                                            float fx, float fy, float fz,
                                            float& f, float& d) {
    float x0 = floorf(fx), y0 = floorf(fy), z0 = floorf(fz);
    float wx = fx - x0, wy = fy - y0, wz = fz - z0;
    int base = ((int)z0 << 14) + ((int)y0 << 7) + (int)x0;
    const float* p_ = img + base;
    float f000 = __ldg(p_), f001 = __ldg(p_ + 1);
    float f010 = __ldg(p_ + 128), f011 = __ldg(p_ + 129);
    float f100 = __ldg(p_ + 16384), f101 = __ldg(p_ + 16385);
    float f110 = __ldg(p_ + 16512), f111 = __ldg(p_ + 16513);
    const float* q_ = opa + base;
    float d000 = __ldg(q_), d001 = __ldg(q_ + 1);
    float d010 = __ldg(q_ + 128), d011 = __ldg(q_ + 129);
    float d100 = __ldg(q_ + 16384), d101 = __ldg(q_ + 16385);
    float d110 = __ldg(q_ + 16512), d111 = __ldg(q_ + 16513);
    float f00 = lerpf(f000, f001, wx), f01 = lerpf(f010, f011, wx);
    float f10 = lerpf(f100, f101, wx), f11 = lerpf(f110, f111, wx);
    float d00 = lerpf(d000, d001, wx), d01 = lerpf(d010, d011, wx);
    float d10 = lerpf(d100, d101, wx), d11 = lerpf(d110, d111, wx);
    float f0 = lerpf(f00, f01, wy), f1 = lerpf(f10, f11, wy);
    float d0 = lerpf(d00, d01, wy), d1 = lerpf(d10, d11, wy);
    f = lerpf(f0, f1, wz);
    d = lerpf(d0, d1, wz);
}

// -------- general sample: 3-way classified, fully inline ------------------
__device__ __forceinline__ void sample_any(const float* __restrict__ img,
                                           const float* __restrict__ opa,
                                           float fx, float fy, float fz,
                                           float& f, float& d) {
    if (fx >= 0.f && fx < 127.f && fy >= 0.f && fy < 127.f && fz >= 0.f &&
        fz < 127.f) {
        sample_fast(img, opa, fx, fy, fz, f, d);
    } else if (fx > -1.f && fx < 128.f && fy > -1.f && fy < 128.f &&
               fz > -1.f && fz < 128.f) {
        // boundary shell: inline predicated per-corner path
        float x0 = floorf(fx), y0 = floorf(fy), z0 = floorf(fz);
        int ix = (int)x0, iy = (int)y0, iz = (int)z0;
        float wx = fx - x0, wy = fy - y0, wz = fz - z0;
        f = 0.f;
        d = 0.f;
#pragma unroll
        for (int dz = 0; dz < 2; dz++) {
#pragma unroll
            for (int dy = 0; dy < 2; dy++) {
#pragma unroll
                for (int dx = 0; dx < 2; dx++) {
                    int X = ix + dx, Y = iy + dy, Z = iz + dz;
                    if ((unsigned)X < 128u && (unsigned)Y < 128u &&
                        (unsigned)Z < 128u) {
                        float wt = (dx ? wx : 1.f - wx) *
                                   (dy ? wy : 1.f - wy) *
                                   (dz ? wz : 1.f - wz);
                        int idx = (Z << 14) + (Y << 7) + X;
                        f += wt * __ldg(img + idx);
                        d += wt * __ldg(opa + idx);
                    }
                }
            }
        }
    } else {
        f = 0.f;
        d = 0.f;
    }
}

// slab interval helper: t range where all coords are within [lo, hi]
__device__ __forceinline__ void slab(float a, float b, float lo, float hi,
                                     float& tlo, float& thi) {
    if (fabsf(a) > 1e-12f) {
        float t1 = (lo - b) / a;
        float t2 = (hi - b) / a;
        tlo = fmaxf(tlo, fminf(t1, t2));
        thi = fminf(thi, fmaxf(t1, t2));
    } else if (b <= lo || b >= hi) {
        tlo = 1e30f;
        thi = -1e30f;
    }
}

// -------- fused render + in-block combine + stats --------
// grid: (4 w-groups, 128 rows); block: 1024 threads = 32 warps.
// warp s = segment s of 32 adjacent-w rays; lane = w. Identical per-warp
// workload to the proven R12 kernel (8 pts/thread, 524K threads).
__global__ void __launch_bounds__(1024)
render_kernel(const float* __restrict__ img, const float* __restrict__ opa,
              const float* __restrict__ Rm, const float* __restrict__ Tv) {
    int lane = threadIdx.x & 31;
    int segIdx = threadIdx.x >> 5;  // 0..31, one warp per segment
    int w = blockIdx.x * 32 + lane;
    int h = blockIdx.y;

    // NDC grid: xs = linspace(1,-1,128) over w; ys likewise over h
    float gx = 1.f + (float)w * (-2.f / 127.f);
    float gy = 1.f + (float)h * (-2.f / 127.f);
    const float INV_FOCAL = 1.f / 1.7320508f;
    float dc0 = gx * INV_FOCAL, dc1 = gy * INV_FOCAL;  // dc2 = 1

    float R00 = Rm[0], R01 = Rm[1], R02 = Rm[2];
    float R10 = Rm[3], R11 = Rm[4], R12 = Rm[5];
    float R20 = Rm[6], R21 = Rm[7], R22 = Rm[8];
    float T0 = Tv[0], T1 = Tv[1], T2 = Tv[2];

    float dwx = dc0 * R00 + dc1 * R01 + R02;
    float dwy = dc0 * R10 + dc1 * R11 + R12;
    float dwz = dc0 * R20 + dc1 * R21 + R22;
    float ox = -(T0 * R00 + T1 * R01 + T2 * R02);
    float oy = -(T0 * R10 + T1 * R11 + T2 * R12);
    float oz = -(T0 * R20 + T1 * R21 + T2 * R22);

    // sample coord: fx = ((pos/half_extent)+1)*0.5*127 = pos*s + 63.5
    const float HE = 1.48828125f;  // (3/128)*127/2
    const float s = 63.5f / HE;
    float ax = dwx * s, bx = ox * s + 63.5f;
    float ay = dwy * s, by = oy * s + 63.5f;
    float az = dwz * s, bz = oz * s + 63.5f;

    int p0 = segIdx * PTS_PER_SEG;
    float dmin = 2.f + (float)p0 * (4.f / 255.f);
    float dmax = 2.f + (float)(p0 + PTS_PER_SEG - 1) * (4.f / 255.f);

    // conservative depth intervals: t_any (zero outside, margin expands)
    // and t_int (fast-path-safe inside, margin shrinks)
    float talo = -1e30f, tahi = 1e30f;
    float tilo = -1e30f, tihi = 1e30f;
    slab(ax, bx, -1.01f, 128.01f, talo, tahi);
    slab(ay, by, -1.01f, 128.01f, talo, tahi);
    slab(az, bz, -1.01f, 128.01f, talo, tahi);
    slab(ax, bx, 0.002f, 126.998f, tilo, tihi);
    slab(ay, by, 0.002f, 126.998f, tilo, tihi);
    slab(az, bz, 0.002f, 126.998f, tilo, tihi);

    float Tt = 1.f, acc = 0.f;

    if (dmax < talo || dmin > tahi) {
        // fully outside: (0,1) identity — skip all work
    } else if (dmin >= tilo && dmax <= tihi) {
        // whole segment interior: branch-free fast loop
#pragma unroll
        for (int g = 0; g < PTS_PER_SEG / 4; g++) {
            float fv[4], dv[4];
#pragma unroll
            for (int k = 0; k < 4; k++) {
                int p = p0 + g * 4 + k;
                float depth = 2.f + (float)p * (4.f / 255.f);
                sample_fast(img, opa, ax * depth + bx, ay * depth + by,
                            az * depth + bz, fv[k], dv[k]);
                dv[k] *= 0.1f;  // densities = opacity * SCALING
            }
#pragma unroll
            for (int k = 0; k < 4; k++) {
                // (1.0 + 1e-10) == 1.0f in fp32 (matches JAX fp32 trace)
                acc = fmaf(fv[k] * dv[k], Tt, acc);
                Tt *= (1.f - dv[k]);
            }
        }
    } else {
        // mixed segment: per-point 3-way classification
#pragma unroll
        for (int g = 0; g < PTS_PER_SEG / 4; g++) {
            float fv[4], dv[4];
#pragma unroll
            for (int k = 0; k < 4; k++) {
                int p = p0 + g * 4 + k;
                float depth = 2.f + (float)p * (4.f / 255.f);
                sample_any(img, opa, ax * depth + bx, ay * depth + by,
                           az * depth + bz, fv[k], dv[k]);
                dv[k] *= 0.1f;
            }
#pragma unroll
            for (int k = 0; k < 4; k++) {
                acc = fmaf(fv[k] * dv[k], Tt, acc);
                Tt *= (1.f - dv[k]);
            }
        }
    }

    // ---- in-block combine via smem (replaces the combine kernel) ----
    __shared__ float2 s_part[NSEG][32];
    s_part[segIdx][lane] = make_float2(acc, Tt);
    __syncthreads();

    if (threadIdx.x < 32) {
        float gray = 0.f, Tc = 1.f;
#pragma unroll
        for (int s2 = 0; s2 < NSEG; s2++) {
            float2 v = s_part[s2][lane];
            gray = fmaf(v.x, Tc, gray);
            Tc *= v.y;
        }
        g_gray[h * 128 + w] = gray;

        // warp reduction over the 32 rays of this block
        double sm = (double)gray;
        double sq = (double)gray * (double)gray;
        float mn = gray, mx = gray;
#pragma unroll
        for (int off = 16; off > 0; off >>= 1) {
            sm += __shfl_down_sync(0xFFFFFFFFu, sm, off);
            sq += __shfl_down_sync(0xFFFFFFFFu, sq, off);
            mn = fminf(mn, __shfl_down_sync(0xFFFFFFFFu, mn, off));
            mx = fmaxf(mx, __shfl_down_sync(0xFFFFFFFFu, mx, off));
        }
        if (lane == 0) {
            atomicAdd(&g_sum, sm);
            atomicAdd(&g_sumsq, sq);
            atomicMin(&g_minkey, fkey(mn));
            atomicMax(&g_maxkey, fkey(mx));
        }
    }
}

// -------- parallel normalize + transpose (16 blocks x 256, one tile each) --
__global__ void __launch_bounds__(256) finalize_kernel(float* __restrict__ out) {
    // read the gray tile FIRST so its loads overlap the stats-load latency
    __shared__ float tile[32 * 33];
    int lane = threadIdx.x & 31, wid = threadIdx.x >> 5;
    int th = (blockIdx.x >> 2) * 32;
    int tw = (blockIdx.x & 3) * 32;
    float v[4];
#pragma unroll
    for (int i = 0; i < 4; i++) {
        int rr = wid * 4 + i;
        v[i] = g_gray[(th + rr) * 128 + tw + lane];
    }

    double sum = g_sum, sumsq = g_sumsq;
    double mean = sum / 16384.0;
    double var = (sumsq - sum * sum / 16384.0) / 16383.0;
    float stddev = (float)sqrt(var > 0.0 ? var : 0.0);
    float gmin = funkey(g_minkey), gmax = funkey(g_maxkey);
    float fmean = (float)mean;
    float inv = 1.f / (stddev + 1e-8f);
    float stmin = (gmin - fmean) * inv;
    float stmax = (gmax - fmean) * inv;
    float rng = 1.f / (stmax - stmin + 1e-8f);

#pragma unroll
    for (int i = 0; i < 4; i++) {
        int rr = wid * 4 + i;
        float vn = (v[i] - fmean) * inv;
        tile[rr * 33 + lane] = (vn - stmin + 1e-8f) * rng;
    }
    __syncthreads();
#pragma unroll
    for (int i = 0; i < 4; i++) {
        int rr = wid * 4 + i;
        out[(tw + rr) * 128 + th + lane] = tile[lane * 33 + rr];
    }

    __threadfence();
    if (threadIdx.x == 0) {
        unsigned c = atomicAdd(&g_count, 1u);
        if (c == 15u) {
            g_sum = 0.0;
            g_sumsq = 0.0;
            g_minkey = 0xFFFFFFFFu;
            g_maxkey = 0u;
            g_count = 0u;
        }
    }
}

extern "C" void kernel_launch(void* const* d_in, const int* in_sizes, int n_in,
                              void* d_out, int out_size) {
    const float* img = (const float*)d_in[0];  // image3d [1,1,128,128,128]
    const float* opa = (const float*)d_in[1];  // opacity  [1,1,128,128,128]
    const float* Rm = (const float*)d_in[2];   // R [1,3,3]
    const float* Tv = (const float*)d_in[3];   // T [1,3]
    float* out = (float*)d_out;                // [1,1,128,128]

    render_kernel<<<dim3(4, IMG_DIM), 1024>>>(img, opa, Rm, Tv);
    finalize_kernel<<<16, 256>>>(out);
}

// round 15
// speedup vs baseline: 1.3944x; 1.0073x over previous
#include <cuda_runtime.h>
#include <math.h>

#define NRAYS 16384
#define NSEG 32          // segments per ray
#define PTS_PER_SEG 8    // points per segment (NSEG*PTS_PER_SEG = 256)
#define RAYS_PER_BLK 16  // rays per block (block = 512 thr = 16 rays x 32 seg)
#define IMG_DIM 128

// -------- device scratch (no allocations allowed) --------
__device__ float g_gray[NRAYS];
// Initializers are load-bearing: the first invocation reads these, and the
// last finalize block resets them to the same values for replay.
__device__ double g_sum = 0.0, g_sumsq = 0.0;
__device__ unsigned g_minkey = 0xFFFFFFFFu;
__device__ unsigned g_maxkey = 0u;
__device__ unsigned g_count = 0u;

// -------- ordered-float key for atomicMin/Max --------
__device__ __forceinline__ unsigned fkey(float f) {
    unsigned u = __float_as_uint(f);
    return (u & 0x80000000u) ? ~u : (u | 0x80000000u);
}
__device__ __forceinline__ float funkey(unsigned k) {
    return (k & 0x80000000u) ? __uint_as_float(k & 0x7FFFFFFFu)
                             : __uint_as_float(~k);
}

__device__ __forceinline__ float lerpf(float a, float b, float t) {
    return fmaf(t, b - a, a);
}

// -------- interior fast sample: no bounds checks (caller guarantees) ------
__device__ __forceinline__ void sample_fast(const float* __restrict__ img,
                                            const float* __restrict__ opa,
                                            float fx, float fy, float fz,
                                            float& f, float& d) {
    float x0 = floorf(fx), y0 = floorf(fy), z0 = floorf(fz);
    float wx = fx - x0, wy = fy - y0, wz = fz - z0;
    int base = ((int)z0 << 14) + ((int)y0 << 7) + (int)x0;
    const float* p_ = img + base;
    float f000 = __ldg(p_), f001 = __ldg(p_ + 1);
    float f010 = __ldg(p_ + 128), f011 = __ldg(p_ + 129);
    float f100 = __ldg(p_ + 16384), f101 = __ldg(p_ + 16385);
    float f110 = __ldg(p_ + 16512), f111 = __ldg(p_ + 16513);
    const float* q_ = opa + base;
    float d000 = __ldg(q_), d001 = __ldg(q_ + 1);
    float d010 = __ldg(q_ + 128), d011 = __ldg(q_ + 129);
    float d100 = __ldg(q_ + 16384), d101 = __ldg(q_ + 16385);
    float d110 = __ldg(q_ + 16512), d111 = __ldg(q_ + 16513);
    float f00 = lerpf(f000, f001, wx), f01 = lerpf(f010, f011, wx);
    float f10 = lerpf(f100, f101, wx), f11 = lerpf(f110, f111, wx);
    float d00 = lerpf(d000, d001, wx), d01 = lerpf(d010, d011, wx);
    float d10 = lerpf(d100, d101, wx), d11 = lerpf(d110, d111, wx);
    float f0 = lerpf(f00, f01, wy), f1 = lerpf(f10, f11, wy);
    float d0 = lerpf(d00, d01, wy), d1 = lerpf(d10, d11, wy);
    f = lerpf(f0, f1, wz);
    d = lerpf(d0, d1, wz);
}

// -------- general sample: 3-way classified, fully inline ------------------
__device__ __forceinline__ void sample_any(const float* __restrict__ img,
                                           const float* __restrict__ opa,
                                           float fx, float fy, float fz,
                                           float& f, float& d) {
    if (fx >= 0.f && fx < 127.f && fy >= 0.f && fy < 127.f && fz >= 0.f &&
        fz < 127.f) {
        sample_fast(img, opa, fx, fy, fz, f, d);
    } else if (fx > -1.f && fx < 128.f && fy > -1.f && fy < 128.f &&
               fz > -1.f && fz < 128.f) {
        // boundary shell: inline predicated per-corner path
        float x0 = floorf(fx), y0 = floorf(fy), z0 = floorf(fz);
        int ix = (int)x0, iy = (int)y0, iz = (int)z0;
        float wx = fx - x0, wy = fy - y0, wz = fz - z0;
        f = 0.f;
        d = 0.f;
#pragma unroll
        for (int dz = 0; dz < 2; dz++) {
#pragma unroll
            for (int dy = 0; dy < 2; dy++) {
#pragma unroll
                for (int dx = 0; dx < 2; dx++) {
                    int X = ix + dx, Y = iy + dy, Z = iz + dz;
                    if ((unsigned)X < 128u && (unsigned)Y < 128u &&
                        (unsigned)Z < 128u) {
                        float wt = (dx ? wx : 1.f - wx) *
                                   (dy ? wy : 1.f - wy) *
                                   (dz ? wz : 1.f - wz);
                        int idx = (Z << 14) + (Y << 7) + X;
                        f += wt * __ldg(img + idx);
                        d += wt * __ldg(opa + idx);
                    }
                }
            }
        }
    } else {
        f = 0.f;
        d = 0.f;
    }
}

// slab interval helper: t range where all coords are within [lo, hi]
__device__ __forceinline__ void slab(float a, float b, float lo, float hi,
                                     float& tlo, float& thi) {
    if (fabsf(a) > 1e-12f) {
        float t1 = (lo - b) / a;
        float t2 = (hi - b) / a;
        tlo = fmaxf(tlo, fminf(t1, t2));
        thi = fminf(thi, fmaxf(t1, t2));
    } else if (b <= lo || b >= hi) {
        tlo = 1e30f;
        thi = -1e30f;
    }
}

// -------- fused render + in-block combine + stats --------
// grid: (8 w-groups, 128 rows); block: 512 threads = 16 rays x 32 segments.
// Thread = one 8-point segment (same per-thread work as the best R12 kernel);
// 3 blocks/SM at ~40 regs keeps 48 warps/SM, 1024 blocks stream smoothly.
__global__ void __launch_bounds__(512, 3)
render_kernel(const float* __restrict__ img, const float* __restrict__ opa,
              const float* __restrict__ Rm, const float* __restrict__ Tv) {
    int rayIdx = threadIdx.x & 15;   // ray within block (adjacent w)
    int segIdx = threadIdx.x >> 4;   // 0..31 segment
    int w = blockIdx.x * RAYS_PER_BLK + rayIdx;
    int h = blockIdx.y;

    // NDC grid: xs = linspace(1,-1,128) over w; ys likewise over h
    float gx = 1.f + (float)w * (-2.f / 127.f);
    float gy = 1.f + (float)h * (-2.f / 127.f);
    const float INV_FOCAL = 1.f / 1.7320508f;
    float dc0 = gx * INV_FOCAL, dc1 = gy * INV_FOCAL;  // dc2 = 1

    float R00 = Rm[0], R01 = Rm[1], R02 = Rm[2];
    float R10 = Rm[3], R11 = Rm[4], R12 = Rm[5];
    float R20 = Rm[6], R21 = Rm[7], R22 = Rm[8];
    float T0 = Tv[0], T1 = Tv[1], T2 = Tv[2];

    float dwx = dc0 * R00 + dc1 * R01 + R02;
    float dwy = dc0 * R10 + dc1 * R11 + R12;
    float dwz = dc0 * R20 + dc1 * R21 + R22;
    float ox = -(T0 * R00 + T1 * R01 + T2 * R02);
    float oy = -(T0 * R10 + T1 * R11 + T2 * R12);
    float oz = -(T0 * R20 + T1 * R21 + T2 * R22);

    // sample coord: fx = ((pos/half_extent)+1)*0.5*127 = pos*s + 63.5
    const float HE = 1.48828125f;  // (3/128)*127/2
    const float s = 63.5f / HE;
    float ax = dwx * s, bx = ox * s + 63.5f;
    float ay = dwy * s, by = oy * s + 63.5f;
    float az = dwz * s, bz = oz * s + 63.5f;

    int p0 = segIdx * PTS_PER_SEG;
    float dmin = 2.f + (float)p0 * (4.f / 255.f);
    float dmax = 2.f + (float)(p0 + PTS_PER_SEG - 1) * (4.f / 255.f);

    // conservative depth intervals: t_any (zero outside, margin expands)
    // and t_int (fast-path-safe inside, margin shrinks)
    float talo = -1e30f, tahi = 1e30f;
    float tilo = -1e30f, tihi = 1e30f;
    slab(ax, bx, -1.01f, 128.01f, talo, tahi);
    slab(ay, by, -1.01f, 128.01f, talo, tahi);
    slab(az, bz, -1.01f, 128.01f, talo, tahi);
    slab(ax, bx, 0.002f, 126.998f, tilo, tihi);
    slab(ay, by, 0.002f, 126.998f, tilo, tihi);
    slab(az, bz, 0.002f, 126.998f, tilo, tihi);

    float Tt = 1.f, acc = 0.f;

    if (dmax < talo || dmin > tahi) {
        // fully outside: (0,1) identity — skip all work
    } else if (dmin >= tilo && dmax <= tihi) {
        // whole segment interior: branch-free fast loop
#pragma unroll
        for (int g = 0; g < PTS_PER_SEG / 4; g++) {
            float fv[4], dv[4];
#pragma unroll
            for (int k = 0; k < 4; k++) {
                int p = p0 + g * 4 + k;
                float depth = 2.f + (float)p * (4.f / 255.f);
                sample_fast(img, opa, ax * depth + bx, ay * depth + by,
                            az * depth + bz, fv[k], dv[k]);
                dv[k] *= 0.1f;  // densities = opacity * SCALING
            }
#pragma unroll
            for (int k = 0; k < 4; k++) {
                // (1.0 + 1e-10) == 1.0f in fp32 (matches JAX fp32 trace)
                acc = fmaf(fv[k] * dv[k], Tt, acc);
                Tt *= (1.f - dv[k]);
            }
        }
    } else {
        // mixed segment: per-point 3-way classification
#pragma unroll
        for (int g = 0; g < PTS_PER_SEG / 4; g++) {
            float fv[4], dv[4];
#pragma unroll
            for (int k = 0; k < 4; k++) {
                int p = p0 + g * 4 + k;
                float depth = 2.f + (float)p * (4.f / 255.f);
                sample_any(img, opa, ax * depth + bx, ay * depth + by,
                           az * depth + bz, fv[k], dv[k]);
                dv[k] *= 0.1f;
            }
#pragma unroll
            for (int k = 0; k < 4; k++) {
                acc = fmaf(fv[k] * dv[k], Tt, acc);
                Tt *= (1.f - dv[k]);
            }
        }
    }

    // ---- in-block combine via smem (bank-conflict-free, padded rows) ----
    __shared__ float s_acc[NSEG][RAYS_PER_BLK + 1];
    __shared__ float s_tt[NSEG][RAYS_PER_BLK + 1];
    s_acc[segIdx][rayIdx] = acc;
    s_tt[segIdx][rayIdx] = Tt;
    __syncthreads();

    if (threadIdx.x < RAYS_PER_BLK) {
        int rr = threadIdx.x;
        float gray = 0.f, Tc = 1.f;
#pragma unroll
        for (int s2 = 0; s2 < NSEG; s2++) {
            gray = fmaf(s_acc[s2][rr], Tc, gray);
            Tc *= s_tt[s2][rr];
        }
        g_gray[h * 128 + blockIdx.x * RAYS_PER_BLK + rr] = gray;

        // half-warp reduction over the 16 rays of this block
        double sm = (double)gray;
        double sq = (double)gray * (double)gray;
        float mn = gray, mx = gray;
#pragma unroll
        for (int off = 8; off > 0; off >>= 1) {
            sm += __shfl_down_sync(0xFFFFu, sm, off, 16);
            sq += __shfl_down_sync(0xFFFFu, sq, off, 16);
            mn = fminf(mn, __shfl_down_sync(0xFFFFu, mn, off, 16));
            mx = fmaxf(mx, __shfl_down_sync(0xFFFFu, mx, off, 16));
        }
        if (rr == 0) {
            atomicAdd(&g_sum, sm);
            atomicAdd(&g_sumsq, sq);
            atomicMin(&g_minkey, fkey(mn));
            atomicMax(&g_maxkey, fkey(mx));
        }
    }
}

// -------- parallel normalize + transpose (16 blocks x 256, one tile each) --
__global__ void __launch_bounds__(256) finalize_kernel(float* __restrict__ out) {
    // read the gray tile FIRST so its loads overlap the stats-load latency
    __shared__ float tile[32 * 33];
    int lane = threadIdx.x & 31, wid = threadIdx.x >> 5;
    int th = (blockIdx.x >> 2) * 32;
    int tw = (blockIdx.x & 3) * 32;
    float v[4];
#pragma unroll
    for (int i = 0; i < 4; i++) {
        int rr = wid * 4 + i;
        v[i] = g_gray[(th + rr) * 128 + tw + lane];
    }

    double sum = g_sum, sumsq = g_sumsq;
    double mean = sum / 16384.0;
    double var = (sumsq - sum * sum / 16384.0) / 16383.0;
    float stddev = (float)sqrt(var > 0.0 ? var : 0.0);
    float gmin = funkey(g_minkey), gmax = funkey(g_maxkey);
    float fmean = (float)mean;
    float inv = 1.f / (stddev + 1e-8f);
    float stmin = (gmin - fmean) * inv;
    float stmax = (gmax - fmean) * inv;
    float rng = 1.f / (stmax - stmin + 1e-8f);

#pragma unroll
    for (int i = 0; i < 4; i++) {
        int rr = wid * 4 + i;
        float vn = (v[i] - fmean) * inv;
        tile[rr * 33 + lane] = (vn - stmin + 1e-8f) * rng;
    }
    __syncthreads();
#pragma unroll
    for (int i = 0; i < 4; i++) {
        int rr = wid * 4 + i;
        out[(tw + rr) * 128 + th + lane] = tile[lane * 33 + rr];
    }

    __threadfence();
    if (threadIdx.x == 0) {
        unsigned c = atomicAdd(&g_count, 1u);
        if (c == 15u) {
            g_sum = 0.0;
            g_sumsq = 0.0;
            g_minkey = 0xFFFFFFFFu;
            g_maxkey = 0u;
            g_count = 0u;
        }
    }
}

extern "C" void kernel_launch(void* const* d_in, const int* in_sizes, int n_in,
                              void* d_out, int out_size) {
    const float* img = (const float*)d_in[0];  // image3d [1,1,128,128,128]
    const float* opa = (const float*)d_in[1];  // opacity  [1,1,128,128,128]
    const float* Rm = (const float*)d_in[2];   // R [1,3,3]
    const float* Tv = (const float*)d_in[3];   // T [1,3]
    float* out = (float*)d_out;                // [1,1,128,128]

    render_kernel<<<dim3(8, IMG_DIM), 512>>>(img, opa, Rm, Tv);
    finalize_kernel<<<16, 256>>>(out);
}

// round 16
// speedup vs baseline: 1.4990x; 1.0750x over previous
#include <cuda_runtime.h>
#include <math.h>

#define NRAYS 16384
#define NSEG 32
#define PTS_PER_SEG 8
#define IMG_DIM 128

// -------- device scratch (no allocations allowed) --------
__device__ float2 g_seg[NSEG * NRAYS];  // (acc, transmittance) per ray-segment
__device__ float g_gray[NRAYS];
// Initializers are load-bearing: the first invocation reads these, and the
// last finalize block resets them to the same values for replay.
__device__ double g_sum = 0.0, g_sumsq = 0.0;
__device__ unsigned g_minkey = 0xFFFFFFFFu;
__device__ unsigned g_maxkey = 0u;
__device__ unsigned g_count = 0u;

// -------- ordered-float key for atomicMin/Max --------
__device__ __forceinline__ unsigned fkey(float f) {
    unsigned u = __float_as_uint(f);
    return (u & 0x80000000u) ? ~u : (u | 0x80000000u);
}
__device__ __forceinline__ float funkey(unsigned k) {
    return (k & 0x80000000u) ? __uint_as_float(k & 0x7FFFFFFFu)
                             : __uint_as_float(~k);
}

__device__ __forceinline__ float lerpf(float a, float b, float t) {
    return fmaf(t, b - a, a);
}

// -------- interior fast sample: no bounds checks (caller guarantees) ------
__device__ __forceinline__ void sample_fast(const float* __restrict__ img,
                                            const float* __restrict__ opa,
                                            float fx, float fy, float fz,
                                            float& f, float& d) {
    float x0 = floorf(fx), y0 = floorf(fy), z0 = floorf(fz);
    float wx = fx - x0, wy = fy - y0, wz = fz - z0;
    int base = ((int)z0 << 14) + ((int)y0 << 7) + (int)x0;
    const float* p_ = img + base;
    float f000 = __ldg(p_), f001 = __ldg(p_ + 1);
    float f010 = __ldg(p_ + 128), f011 = __ldg(p_ + 129);
    float f100 = __ldg(p_ + 16384), f101 = __ldg(p_ + 16385);
    float f110 = __ldg(p_ + 16512), f111 = __ldg(p_ + 16513);
    const float* q_ = opa + base;
    float d000 = __ldg(q_), d001 = __ldg(q_ + 1);
    float d010 = __ldg(q_ + 128), d011 = __ldg(q_ + 129);
    float d100 = __ldg(q_ + 16384), d101 = __ldg(q_ + 16385);
    float d110 = __ldg(q_ + 16512), d111 = __ldg(q_ + 16513);
    float f00 = lerpf(f000, f001, wx), f01 = lerpf(f010, f011, wx);
    float f10 = lerpf(f100, f101, wx), f11 = lerpf(f110, f111, wx);
    float d00 = lerpf(d000, d001, wx), d01 = lerpf(d010, d011, wx);
    float d10 = lerpf(d100, d101, wx), d11 = lerpf(d110, d111, wx);
    float f0 = lerpf(f00, f01, wy), f1 = lerpf(f10, f11, wy);
    float d0 = lerpf(d00, d01, wy), d1 = lerpf(d10, d11, wy);
    f = lerpf(f0, f1, wz);
    d = lerpf(d0, d1, wz);
}

// -------- general sample: 3-way classified, fully inline ------------------
__device__ __forceinline__ void sample_any(const float* __restrict__ img,
                                           const float* __restrict__ opa,
                                           float fx, float fy, float fz,
                                           float& f, float& d) {
    if (fx >= 0.f && fx < 127.f && fy >= 0.f && fy < 127.f && fz >= 0.f &&
        fz < 127.f) {
        sample_fast(img, opa, fx, fy, fz, f, d);
    } else if (fx > -1.f && fx < 128.f && fy > -1.f && fy < 128.f &&
               fz > -1.f && fz < 128.f) {
        // boundary shell: inline predicated per-corner path
        float x0 = floorf(fx), y0 = floorf(fy), z0 = floorf(fz);
        int ix = (int)x0, iy = (int)y0, iz = (int)z0;
        float wx = fx - x0, wy = fy - y0, wz = fz - z0;
        f = 0.f;
        d = 0.f;
#pragma unroll
        for (int dz = 0; dz < 2; dz++) {
#pragma unroll
            for (int dy = 0; dy < 2; dy++) {
#pragma unroll
                for (int dx = 0; dx < 2; dx++) {
                    int X = ix + dx, Y = iy + dy, Z = iz + dz;
                    if ((unsigned)X < 128u && (unsigned)Y < 128u &&
                        (unsigned)Z < 128u) {
                        float wt = (dx ? wx : 1.f - wx) *
                                   (dy ? wy : 1.f - wy) *
                                   (dz ? wz : 1.f - wz);
                        int idx = (Z << 14) + (Y << 7) + X;
                        f += wt * __ldg(img + idx);
                        d += wt * __ldg(opa + idx);
                    }
                }
            }
        }
    } else {
        f = 0.f;
        d = 0.f;
    }
}

// slab interval helper: t range where all coords are within [lo, hi]
__device__ __forceinline__ void slab(float a, float b, float lo, float hi,
                                     float& tlo, float& thi) {
    if (fabsf(a) > 1e-12f) {
        float t1 = (lo - b) / a;
        float t2 = (hi - b) / a;
        tlo = fmaxf(tlo, fminf(t1, t2));
        thi = fminf(thi, fmaxf(t1, t2));
    } else if (b <= lo || b >= hi) {
        tlo = 1e30f;
        thi = -1e30f;
    }
}

// -------- per-(ray,segment) rendering, warp-uniform classification --------
// grid: (NSEG, 128 rows), block: 128 threads (one per pixel column w)
__global__ void __launch_bounds__(128)
render_kernel(const float* __restrict__ img, const float* __restrict__ opa,
              const float* __restrict__ Rm, const float* __restrict__ Tv) {
    int w = threadIdx.x;
    int seg = blockIdx.x;
    int h = blockIdx.y;

    // NDC grid: xs = linspace(1,-1,128) over w; ys likewise over h
    float gx = 1.f + (float)w * (-2.f / 127.f);
    float gy = 1.f + (float)h * (-2.f / 127.f);
    const float INV_FOCAL = 1.f / 1.7320508f;
    float dc0 = gx * INV_FOCAL, dc1 = gy * INV_FOCAL;  // dc2 = 1

    float R00 = Rm[0], R01 = Rm[1], R02 = Rm[2];
    float R10 = Rm[3], R11 = Rm[4], R12 = Rm[5];
    float R20 = Rm[6], R21 = Rm[7], R22 = Rm[8];
    float T0 = Tv[0], T1 = Tv[1], T2 = Tv[2];

    float dwx = dc0 * R00 + dc1 * R01 + R02;
    float dwy = dc0 * R10 + dc1 * R11 + R12;
    float dwz = dc0 * R20 + dc1 * R21 + R22;
    float ox = -(T0 * R00 + T1 * R01 + T2 * R02);
    float oy = -(T0 * R10 + T1 * R11 + T2 * R12);
    float oz = -(T0 * R20 + T1 * R21 + T2 * R22);

    // sample coord: fx = ((pos/half_extent)+1)*0.5*127 = pos*s + 63.5
    const float HE = 1.48828125f;  // (3/128)*127/2
    const float s = 63.5f / HE;
    float ax = dwx * s, bx = ox * s + 63.5f;
    float ay = dwy * s, by = oy * s + 63.5f;
    float az = dwz * s, bz = oz * s + 63.5f;

    int r = h * 128 + w;
    int p0 = seg * PTS_PER_SEG;
    float dmin = 2.f + (float)p0 * (4.f / 255.f);
    float dmax = 2.f + (float)(p0 + PTS_PER_SEG - 1) * (4.f / 255.f);

    // conservative depth intervals: t_any (zero outside, margin expands)
    // and t_int (fast-path-safe inside, margin shrinks)
    float talo = -1e30f, tahi = 1e30f;
    float tilo = -1e30f, tihi = 1e30f;
    slab(ax, bx, -1.01f, 128.01f, talo, tahi);
    slab(ay, by, -1.01f, 128.01f, talo, tahi);
    slab(az, bz, -1.01f, 128.01f, talo, tahi);
    slab(ax, bx, 0.002f, 126.998f, tilo, tihi);
    slab(ay, by, 0.002f, 126.998f, tilo, tihi);
    slab(az, bz, 0.002f, 126.998f, tilo, tihi);

    bool seg_out = (dmax < talo || dmin > tahi);
    bool seg_int = (dmin >= tilo && dmax <= tihi);

    float Tt = 1.f, acc = 0.f;
    const unsigned FULL = 0xFFFFFFFFu;

    // ---- warp-uniform path selection: each warp executes exactly ONE loop.
    if (!__all_sync(FULL, seg_out)) {
        if (__all_sync(FULL, seg_int)) {
            // whole warp interior: branch-free fast loop, no dead lanes
#pragma unroll
            for (int g = 0; g < PTS_PER_SEG / 4; g++) {
                float fv[4], dv[4];
#pragma unroll
                for (int k = 0; k < 4; k++) {
                    int p = p0 + g * 4 + k;
                    float depth = 2.f + (float)p * (4.f / 255.f);
                    sample_fast(img, opa, ax * depth + bx, ay * depth + by,
                                az * depth + bz, fv[k], dv[k]);
                    dv[k] *= 0.1f;  // densities = opacity * SCALING
                }
#pragma unroll
                for (int k = 0; k < 4; k++) {
                    // (1.0 + 1e-10) == 1.0f in fp32 (matches JAX fp32 trace)
                    acc = fmaf(fv[k] * dv[k], Tt, acc);
                    Tt *= (1.f - dv[k]);
                }
            }
        } else {
            // mixed warp: single per-point-classified loop for all lanes
            // (outside lanes produce exact zeros inside sample_any)
#pragma unroll
            for (int g = 0; g < PTS_PER_SEG / 4; g++) {
                float fv[4], dv[4];
#pragma unroll
                for (int k = 0; k < 4; k++) {
                    int p = p0 + g * 4 + k;
                    float depth = 2.f + (float)p * (4.f / 255.f);
                    sample_any(img, opa, ax * depth + bx, ay * depth + by,
                               az * depth + bz, fv[k], dv[k]);
                    dv[k] *= 0.1f;
                }
#pragma unroll
                for (int k = 0; k < 4; k++) {
                    acc = fmaf(fv[k] * dv[k], Tt, acc);
                    Tt *= (1.f - dv[k]);
                }
            }
        }
    }
    // whole-warp-outside: falls through with (0,1) identity

    g_seg[seg * NRAYS + r] = make_float2(acc, Tt);
}

// -------- combine segments + accumulate global stats (64 blocks x 256) ----
__global__ void __launch_bounds__(256) combine_stats_kernel() {
    int r = blockIdx.x * blockDim.x + threadIdx.x;
    float gray = 0.f;
    float Tt = 1.f;
#pragma unroll
    for (int s2 = 0; s2 < NSEG; s2++) {
        float2 v = g_seg[s2 * NRAYS + r];
        gray = fmaf(v.x, Tt, gray);
        Tt *= v.y;
    }
    g_gray[r] = gray;

    double sm = (double)gray;
    double sq = (double)gray * (double)gray;
    float mn = gray, mx = gray;
#pragma unroll
    for (int off = 16; off > 0; off >>= 1) {
        sm += __shfl_down_sync(0xFFFFFFFFu, sm, off);
        sq += __shfl_down_sync(0xFFFFFFFFu, sq, off);
        mn = fminf(mn, __shfl_down_sync(0xFFFFFFFFu, mn, off));
        mx = fmaxf(mx, __shfl_down_sync(0xFFFFFFFFu, mx, off));
    }
    __shared__ double s_sm[8], s_sq[8];
    __shared__ float s_mn[8], s_mx[8];
    int lane = threadIdx.x & 31, wid = threadIdx.x >> 5;
    if (lane == 0) {
        s_sm[wid] = sm;
        s_sq[wid] = sq;
        s_mn[wid] = mn;
        s_mx[wid] = mx;
    }
    __syncthreads();
    if (wid == 0) {
        sm = (lane < 8) ? s_sm[lane] : 0.0;
        sq = (lane < 8) ? s_sq[lane] : 0.0;
        mn = (lane < 8) ? s_mn[lane] : 3.0e38f;
        mx = (lane < 8) ? s_mx[lane] : -3.0e38f;
#pragma unroll
        for (int off = 4; off > 0; off >>= 1) {
            sm += __shfl_down_sync(0xFFFFFFFFu, sm, off);
            sq += __shfl_down_sync(0xFFFFFFFFu, sq, off);
            mn = fminf(mn, __shfl_down_sync(0xFFFFFFFFu, mn, off));
            mx = fmaxf(mx, __shfl_down_sync(0xFFFFFFFFu, mx, off));
        }
        if (lane == 0) {
            atomicAdd(&g_sum, sm);
            atomicAdd(&g_sumsq, sq);
            atomicMin(&g_minkey, fkey(mn));
            atomicMax(&g_maxkey, fkey(mx));
        }
    }
}

// -------- parallel normalize + transpose (16 blocks x 256, one tile each) --
__global__ void __launch_bounds__(256) finalize_kernel(float* __restrict__ out) {
    // read the gray tile FIRST so its loads overlap the stats-load latency
    __shared__ float tile[32 * 33];
    int lane = threadIdx.x & 31, wid = threadIdx.x >> 5;
    int th = (blockIdx.x >> 2) * 32;
    int tw = (blockIdx.x & 3) * 32;
    float v[4];
#pragma unroll
    for (int i = 0; i < 4; i++) {
        int rr = wid * 4 + i;
        v[i] = g_gray[(th + rr) * 128 + tw + lane];
    }

    double sum = g_sum, sumsq = g_sumsq;
    double mean = sum / 16384.0;
    double var = (sumsq - sum * sum / 16384.0) / 16383.0;
    float stddev = (float)sqrt(var > 0.0 ? var : 0.0);
    float gmin = funkey(g_minkey), gmax = funkey(g_maxkey);
    float fmean = (float)mean;
    float inv = 1.f / (stddev + 1e-8f);
    float stmin = (gmin - fmean) * inv;
    float stmax = (gmax - fmean) * inv;
    float rng = 1.f / (stmax - stmin + 1e-8f);

#pragma unroll
    for (int i = 0; i < 4; i++) {
        int rr = wid * 4 + i;
        float vn = (v[i] - fmean) * inv;
        tile[rr * 33 + lane] = (vn - stmin + 1e-8f) * rng;
    }
    __syncthreads();
#pragma unroll
    for (int i = 0; i < 4; i++) {
        int rr = wid * 4 + i;
        out[(tw + rr) * 128 + th + lane] = tile[lane * 33 + rr];
    }

    __threadfence();
    if (threadIdx.x == 0) {
        unsigned c = atomicAdd(&g_count, 1u);
        if (c == 15u) {
            g_sum = 0.0;
            g_sumsq = 0.0;
            g_minkey = 0xFFFFFFFFu;
            g_maxkey = 0u;
            g_count = 0u;
        }
    }
}

extern "C" void kernel_launch(void* const* d_in, const int* in_sizes, int n_in,
                              void* d_out, int out_size) {
    const float* img = (const float*)d_in[0];  // image3d [1,1,128,128,128]
    const float* opa = (const float*)d_in[1];  // opacity  [1,1,128,128,128]
    const float* Rm = (const float*)d_in[2];   // R [1,3,3]
    const float* Tv = (const float*)d_in[3];   // T [1,3]
    float* out = (float*)d_out;                // [1,1,128,128]

    render_kernel<<<dim3(NSEG, IMG_DIM), 128>>>(img, opa, Rm, Tv);
    combine_stats_kernel<<<64, 256>>>();
    finalize_kernel<<<16, 256>>>(out);
}